// round 7
// baseline (speedup 1.0000x reference)
#include <cuda_runtime.h>
#include <cuda_bf16.h>
#include <math.h>
#include <stdint.h>

#define BB 2
#define TT 2048
#define CC 1024
#define HH 16
#define HD 64
#define C3 3072

// fp32 scratch
__device__ float g_qkv[(size_t)BB * TT * C3];   // 4096 x 3072

// pre-split bf16 hi/lo buffers (packed as uint = 2 halves)
__device__ unsigned g_xh[2097152],  g_xl[2097152];    // x      4096x1024
__device__ unsigned g_wqh[1572864], g_wql[1572864];   // w_qkv  3072x1024
__device__ unsigned g_woh[524288],  g_wol[524288];    // w_out  1024x1024
__device__ unsigned g_qh[2097152],  g_ql[2097152];    // Q  [b,h,t,d]
__device__ unsigned g_kh[2097152],  g_kl[2097152];    // K  [b,h,t,d]
__device__ unsigned g_vh[2097152],  g_vl[2097152];    // V  [b,h,t,d]
__device__ unsigned g_aoh[2097152], g_aol[2097152];   // attn out 4096x1024

// ---------------------------------------------------------------------------
// helpers
// ---------------------------------------------------------------------------
__device__ __forceinline__ void mma_bf16(float* c, const unsigned* a, const unsigned* b) {
    asm("mma.sync.aligned.m16n8k16.row.col.f32.bf16.bf16.f32 "
        "{%0,%1,%2,%3},{%4,%5,%6,%7},{%8,%9},{%0,%1,%2,%3};"
        : "+f"(c[0]), "+f"(c[1]), "+f"(c[2]), "+f"(c[3])
        : "r"(a[0]), "r"(a[1]), "r"(a[2]), "r"(a[3]), "r"(b[0]), "r"(b[1]));
}
__device__ __forceinline__ void ldm_x4(unsigned* r, uint32_t addr) {
    asm volatile("ldmatrix.sync.aligned.m8n8.x4.shared.b16 {%0,%1,%2,%3}, [%4];"
                 : "=r"(r[0]), "=r"(r[1]), "=r"(r[2]), "=r"(r[3]) : "r"(addr));
}
__device__ __forceinline__ void ldm_x4t(unsigned* r, uint32_t addr) {
    asm volatile("ldmatrix.sync.aligned.m8n8.x4.trans.shared.b16 {%0,%1,%2,%3}, [%4];"
                 : "=r"(r[0]), "=r"(r[1]), "=r"(r[2]), "=r"(r[3]) : "r"(addr));
}
__device__ __forceinline__ unsigned pack2bf(float lo, float hi) {
    unsigned r;
    asm("cvt.rn.bf16x2.f32 %0, %1, %2;" : "=r"(r) : "f"(hi), "f"(lo));
    return r;
}
__device__ __forceinline__ float bflo(unsigned u) { return __uint_as_float(u << 16); }
__device__ __forceinline__ float bfhi(unsigned u) { return __uint_as_float(u & 0xffff0000u); }

__device__ __forceinline__ void cpa16(uint32_t dst, const void* src) {
    asm volatile("cp.async.ca.shared.global [%0], [%1], 16;" :: "r"(dst), "l"(src));
}
#define CP_COMMIT asm volatile("cp.async.commit_group;" ::: "memory")
#define CP_WAIT0  asm volatile("cp.async.wait_group 0;" ::: "memory")

// fast exp on fma/alu pipes (no MUFU)
__device__ __forceinline__ float fexp(float x) {
    float y = x * 1.4426950408889634f;
    y = fmaxf(y, -126.0f);
    int ni = __float2int_rd(y);
    float f = y - (float)ni;
    float p = 0.0018775767f;
    p = fmaf(p, f, 0.0089893397f);
    p = fmaf(p, f, 0.0558282185f);
    p = fmaf(p, f, 0.2400789568f);
    p = fmaf(p, f, 0.6931531203f);
    p = fmaf(p, f, 0.9999999702f);
    return __uint_as_float(__float_as_uint(p) + ((unsigned)ni << 23));
}

__device__ __forceinline__ void split2(float a, float b, unsigned& hp, unsigned& lp) {
    hp = pack2bf(a, b);
    lp = pack2bf(a - bflo(hp), b - bfhi(hp));
}

// ---------------------------------------------------------------------------
// conversion kernels
// ---------------------------------------------------------------------------
__global__ void convert_pair(const float4* __restrict__ src,
                             uint2* __restrict__ dsth, uint2* __restrict__ dstl, int n4)
{
    int i = blockIdx.x * blockDim.x + threadIdx.x;
    if (i >= n4) return;
    float4 v = src[i];
    unsigned h01, l01, h23, l23;
    split2(v.x, v.y, h01, l01);
    split2(v.z, v.w, h23, l23);
    dsth[i] = make_uint2(h01, h23);
    dstl[i] = make_uint2(l01, l23);
}

// RoPE + scale fold + hi/lo split + head-major transpose, one pass
__global__ void convert_qkv_rope()
{
    int i = blockIdx.x * blockDim.x + threadIdx.x;
    const int total = BB * TT * HH * 32;
    if (i >= total) return;

    int n = i >> 9;          // token
    int r = i & 511;
    int h = r >> 5;
    int j = r & 31;
    int t = n & (TT - 1);
    int b = n >> 11;

    const float* p = g_qkv + (size_t)n * C3 + h * HD + 2 * j;
    float qr = p[0],      qi = p[1];
    float kr = p[CC],     ki = p[CC + 1];
    float vr = p[2 * CC], vi = p[2 * CC + 1];

    float inv_freq = (float)exp(-(double)j * 0.28782313662425575);
    float f = (float)t * inv_freq;
    float c = cosf(f);
    float s = sinf(f);

    float q0 = (qr * c - qi * s) * 0.125f;   // fold 1/sqrt(64)
    float q1 = (qr * s + qi * c) * 0.125f;
    float k0 = kr * c - ki * s;
    float k1 = kr * s + ki * c;

    size_t o = ((size_t)(b * HH + h) * TT + t) * 32 + j;
    unsigned hp, lp;
    split2(q0, q1, hp, lp); g_qh[o] = hp; g_ql[o] = lp;
    split2(k0, k1, hp, lp); g_kh[o] = hp; g_kl[o] = lp;
    split2(vr, vi, hp, lp); g_vh[o] = hp; g_vl[o] = lp;
}

// ---------------------------------------------------------------------------
// Tensor-core GEMM (NT) on pre-split bf16 hi/lo inputs.
// CTA 256x128, BK=16, 512 threads, warp tile 64x32, cp.async double buffer.
// ---------------------------------------------------------------------------
#define GP 24
#define A_H (256 * GP)
#define B_H (128 * GP)
#define STAGE_H (2 * A_H + 2 * B_H)
#define GEMM_SMEM_BYTES (2 * STAGE_H * 2)   // 73728 B

__global__ __launch_bounds__(512, 1) void gemm_ps(
    const unsigned short* __restrict__ Ah, const unsigned short* __restrict__ Al,
    const unsigned short* __restrict__ Bh, const unsigned short* __restrict__ Bl,
    float* __restrict__ Cout, int M, int N, int K)
{
    extern __shared__ unsigned short sh[];

    const int tid = threadIdx.x;
    const int wid = tid >> 5;
    const int lane = tid & 31;
    const int warp_m = wid >> 2;
    const int warp_n = wid & 3;

    const unsigned short* Aph = Ah + (size_t)blockIdx.y * 256 * K;
    const unsigned short* Apl = Al + (size_t)blockIdx.y * 256 * K;
    const unsigned short* Bph = Bh + (size_t)blockIdx.x * 128 * K;
    const unsigned short* Bpl = Bl + (size_t)blockIdx.x * 128 * K;

    const int arow = tid >> 1, ach = tid & 1;          // A: 256 rows x 2 chunks
    const int brow = (tid & 255) >> 1, bch = tid & 1;  // B: 128 rows x 2 chunks
    const unsigned short* bsrc = (tid < 256) ? Bph : Bpl;
    const uint32_t b_sm_add = (tid < 256) ? (uint32_t)(2 * A_H * 2)
                                          : (uint32_t)((2 * A_H + B_H) * 2);

    const uint32_t smem_u32 = (uint32_t)__cvta_generic_to_shared(sh);

    const int a_lrow = (lane & 7) + ((lane >> 3) & 1) * 8;
    const int a_lcol = ((lane >> 4) & 1) * 8;

    float acc[4][4][4];
#pragma unroll
    for (int i = 0; i < 4; i++)
#pragma unroll
        for (int j = 0; j < 4; j++)
#pragma unroll
            for (int q = 0; q < 4; q++) acc[i][j][q] = 0.f;

    const int nstage = K / 16;

    // prologue: stage 0
    {
        uint32_t d = smem_u32;
        uint32_t doffA = (uint32_t)((arow * GP + ach * 8) * 2);
        cpa16(d + doffA,           Aph + (size_t)arow * K + ach * 8);
        cpa16(d + A_H * 2 + doffA, Apl + (size_t)arow * K + ach * 8);
        cpa16(d + b_sm_add + (uint32_t)((brow * GP + bch * 8) * 2),
              bsrc + (size_t)brow * K + bch * 8);
    }
    CP_COMMIT;
    CP_WAIT0;
    __syncthreads();

    for (int s = 0; s < nstage; s++) {
        if (s + 1 < nstage) {
            uint32_t d = smem_u32 + (unsigned)((s + 1) & 1) * (STAGE_H * 2);
            const int k0 = (s + 1) * 16;
            uint32_t doffA = (uint32_t)((arow * GP + ach * 8) * 2);
            cpa16(d + doffA,           Aph + (size_t)arow * K + k0 + ach * 8);
            cpa16(d + A_H * 2 + doffA, Apl + (size_t)arow * K + k0 + ach * 8);
            cpa16(d + b_sm_add + (uint32_t)((brow * GP + bch * 8) * 2),
                  bsrc + (size_t)brow * K + k0 + bch * 8);
            CP_COMMIT;
        }
        {
            const uint32_t base = smem_u32 + (unsigned)(s & 1) * (STAGE_H * 2);
            const uint32_t baseAhi = base;
            const uint32_t baseAlo = base + A_H * 2;
            const uint32_t baseBhi = base + 2 * A_H * 2;
            const uint32_t baseBlo = base + (2 * A_H + B_H) * 2;

            unsigned Bh2[2][4], Bl2[2][4];
#pragma unroll
            for (int anp = 0; anp < 2; anp++) {
                const uint32_t off = (uint32_t)(((warp_n * 32 + anp * 16 +
                                                  ((lane >> 4) & 1) * 8 + (lane & 7)) * GP +
                                                 ((lane >> 3) & 1) * 8) * 2);
                ldm_x4(Bh2[anp], baseBhi + off);
                ldm_x4(Bl2[anp], baseBlo + off);
            }
#pragma unroll
            for (int am = 0; am < 4; am++) {
                unsigned Ah2[4], Al2[4];
                const uint32_t off =
                    (uint32_t)(((warp_m * 64 + am * 16 + a_lrow) * GP + a_lcol) * 2);
                ldm_x4(Ah2, baseAhi + off);
                ldm_x4(Al2, baseAlo + off);
#pragma unroll
                for (int anp = 0; anp < 2; anp++) {
                    mma_bf16(acc[am][2 * anp],     Ah2, &Bh2[anp][0]);
                    mma_bf16(acc[am][2 * anp + 1], Ah2, &Bh2[anp][2]);
                    mma_bf16(acc[am][2 * anp],     Ah2, &Bl2[anp][0]);
                    mma_bf16(acc[am][2 * anp + 1], Ah2, &Bl2[anp][2]);
                    mma_bf16(acc[am][2 * anp],     Al2, &Bh2[anp][0]);
                    mma_bf16(acc[am][2 * anp + 1], Al2, &Bh2[anp][2]);
                }
            }
        }
        if (s + 1 < nstage) {
            CP_WAIT0;
            __syncthreads();
        }
    }

    const int mbase = blockIdx.y * 256 + warp_m * 64 + (lane >> 2);
    const int nbase = blockIdx.x * 128 + warp_n * 32 + (lane & 3) * 2;
#pragma unroll
    for (int am = 0; am < 4; am++) {
#pragma unroll
        for (int an = 0; an < 4; an++) {
            const int r = mbase + am * 16;
            const int c = nbase + an * 8;
            *(float2*)&Cout[(size_t)r * N + c]       = make_float2(acc[am][an][0], acc[am][an][1]);
            *(float2*)&Cout[(size_t)(r + 8) * N + c] = make_float2(acc[am][an][2], acc[am][an][3]);
        }
    }
}

// ---------------------------------------------------------------------------
// Tensor-core causal flash attention on pre-split K/V, cp.async double buffer.
// CTA: 128 q-rows, 8 warps, 64-key tiles.
// ---------------------------------------------------------------------------
#define GP2 72
#define KV_STAGE_H 18432       // Khi,Klo,Vhi,Vlo @ 4608 halves each
#define KHI_O 0
#define KLO_O 4608
#define VHI_O 9216
#define VLO_O 13824
#define QHI_O 36864
#define QLO_O 46080
#define ATTN_SMEM_HALVES 55296
#define ATTN_SMEM_BYTES (ATTN_SMEM_HALVES * 2)   // 110592 B

__global__ __launch_bounds__(256) void attn_mma()
{
    extern __shared__ unsigned short ash[];

    const int bh = blockIdx.y;      // b*16 + h (head-major buffers indexed by bh)
    const int b = bh >> 4;
    const int h = bh & 15;
    const int qtile = 15 - blockIdx.x;
    const int q0 = qtile * 128;
    const int tid = threadIdx.x;
    const int wid = tid >> 5;
    const int lane = tid & 31;

    const unsigned short* qh_g = (const unsigned short*)g_qh;
    const unsigned short* ql_g = (const unsigned short*)g_ql;
    const unsigned short* kh_g = (const unsigned short*)g_kh;
    const unsigned short* kl_g = (const unsigned short*)g_kl;
    const unsigned short* vh_g = (const unsigned short*)g_vh;
    const unsigned short* vl_g = (const unsigned short*)g_vl;

    const uint32_t sm_u = (uint32_t)__cvta_generic_to_shared(ash);

    const int a_lrow = (lane & 7) + ((lane >> 3) & 1) * 8;
    const int a_lcol = ((lane >> 4) & 1) * 8;

    // ---- prologue: Q (128x64) + KV tile 0 ----
    {
        size_t tbq = ((size_t)bh * TT + q0) * 64;
#pragma unroll
        for (int it = 0; it < 4; it++) {
            int idx = tid + it * 256;          // 1024 chunks per buffer
            int r = idx >> 3, ch = idx & 7;
            uint32_t doff = (uint32_t)((r * GP2 + ch * 8) * 2);
            size_t soff = tbq + (size_t)r * 64 + ch * 8;
            cpa16(sm_u + QHI_O * 2 + doff, qh_g + soff);
            cpa16(sm_u + QLO_O * 2 + doff, ql_g + soff);
        }
        size_t tbk = (size_t)bh * TT * 64;
#pragma unroll
        for (int it = 0; it < 2; it++) {
            int idx = tid + it * 256;          // 512 chunks per buffer
            int r = idx >> 3, ch = idx & 7;
            uint32_t doff = (uint32_t)((r * GP2 + ch * 8) * 2);
            size_t soff = tbk + (size_t)r * 64 + ch * 8;
            cpa16(sm_u + KHI_O * 2 + doff, kh_g + soff);
            cpa16(sm_u + KLO_O * 2 + doff, kl_g + soff);
            cpa16(sm_u + VHI_O * 2 + doff, vh_g + soff);
            cpa16(sm_u + VLO_O * 2 + doff, vl_g + soff);
        }
    }
    CP_COMMIT;
    CP_WAIT0;
    __syncthreads();

    // Q fragments
    unsigned Qh[4][4], Ql[4][4];
#pragma unroll
    for (int kk = 0; kk < 4; kk++) {
        uint32_t off = (uint32_t)(((wid * 16 + a_lrow) * GP2 + kk * 16 + a_lcol) * 2);
        ldm_x4(Qh[kk], sm_u + QHI_O * 2 + off);
        ldm_x4(Ql[kk], sm_u + QLO_O * 2 + off);
    }

    float o[8][4];
#pragma unroll
    for (int nb = 0; nb < 8; nb++)
#pragma unroll
        for (int e = 0; e < 4; e++) o[nb][e] = 0.f;
    float m0 = -1e30f, m1 = -1e30f, l0 = 0.f, l1 = 0.f;

    const int rg0 = q0 + wid * 16 + (lane >> 2);
    const int rg1 = rg0 + 8;
    const int cbase = (lane & 3) * 2;

    const int nkt = 2 * qtile + 2;
    for (int kt = 0; kt < nkt; kt++) {
        // issue next tile
        if (kt + 1 < nkt) {
            uint32_t d = sm_u + (unsigned)((kt + 1) & 1) * (KV_STAGE_H * 2);
            size_t tbk = ((size_t)bh * TT + (kt + 1) * 64) * 64;
#pragma unroll
            for (int it = 0; it < 2; it++) {
                int idx = tid + it * 256;
                int r = idx >> 3, ch = idx & 7;
                uint32_t doff = (uint32_t)((r * GP2 + ch * 8) * 2);
                size_t soff = tbk + (size_t)r * 64 + ch * 8;
                cpa16(d + KHI_O * 2 + doff, kh_g + soff);
                cpa16(d + KLO_O * 2 + doff, kl_g + soff);
                cpa16(d + VHI_O * 2 + doff, vh_g + soff);
                cpa16(d + VLO_O * 2 + doff, vl_g + soff);
            }
            CP_COMMIT;
        }

        const uint32_t kb = sm_u + (unsigned)(kt & 1) * (KV_STAGE_H * 2);
        const uint32_t kh_u = kb + KHI_O * 2;
        const uint32_t kl_u = kb + KLO_O * 2;
        const uint32_t vh_u = kb + VHI_O * 2;
        const uint32_t vl_u = kb + VLO_O * 2;
        const int k0 = kt * 64;

        // ---- S = Q K^T (scale pre-folded into Q) ----
        float s[8][4];
#pragma unroll
        for (int nb = 0; nb < 8; nb++)
#pragma unroll
            for (int e = 0; e < 4; e++) s[nb][e] = 0.f;

#pragma unroll
        for (int kk = 0; kk < 4; kk++) {
#pragma unroll
            for (int nbp = 0; nbp < 4; nbp++) {
                unsigned Bh2[4], Bl2[4];
                uint32_t off = (uint32_t)(((nbp * 16 + ((lane >> 4) & 1) * 8 + (lane & 7)) * GP2 +
                                           kk * 16 + ((lane >> 3) & 1) * 8) * 2);
                ldm_x4(Bh2, kh_u + off);
                ldm_x4(Bl2, kl_u + off);
                mma_bf16(s[2 * nbp],     Qh[kk], &Bh2[0]);
                mma_bf16(s[2 * nbp + 1], Qh[kk], &Bh2[2]);
                mma_bf16(s[2 * nbp],     Qh[kk], &Bl2[0]);
                mma_bf16(s[2 * nbp + 1], Qh[kk], &Bl2[2]);
                mma_bf16(s[2 * nbp],     Ql[kk], &Bh2[0]);
                mma_bf16(s[2 * nbp + 1], Ql[kk], &Bh2[2]);
            }
        }

        // ---- causal mask ----
        const bool diag = (kt >= 2 * qtile);
        if (diag) {
#pragma unroll
            for (int nb = 0; nb < 8; nb++) {
                int c0g = k0 + nb * 8 + cbase;
#pragma unroll
                for (int e = 0; e < 4; e++) {
                    int col = c0g + (e & 1);
                    int row = (e < 2) ? rg0 : rg1;
                    if (col > row) s[nb][e] = -1e30f;
                }
            }
        }

        // ---- online softmax ----
        float mx0 = -1e30f, mx1 = -1e30f;
#pragma unroll
        for (int nb = 0; nb < 8; nb++) {
            mx0 = fmaxf(mx0, fmaxf(s[nb][0], s[nb][1]));
            mx1 = fmaxf(mx1, fmaxf(s[nb][2], s[nb][3]));
        }
        mx0 = fmaxf(mx0, __shfl_xor_sync(0xffffffffu, mx0, 1));
        mx0 = fmaxf(mx0, __shfl_xor_sync(0xffffffffu, mx0, 2));
        mx1 = fmaxf(mx1, __shfl_xor_sync(0xffffffffu, mx1, 1));
        mx1 = fmaxf(mx1, __shfl_xor_sync(0xffffffffu, mx1, 2));

        float nm0 = fmaxf(m0, mx0), nm1 = fmaxf(m1, mx1);
        float corr0 = fexp(m0 - nm0), corr1 = fexp(m1 - nm1);
        m0 = nm0; m1 = nm1;

        float ls0 = 0.f, ls1 = 0.f;
#pragma unroll
        for (int nb = 0; nb < 8; nb++) {
            s[nb][0] = fexp(s[nb][0] - nm0); ls0 += s[nb][0];
            s[nb][1] = fexp(s[nb][1] - nm0); ls0 += s[nb][1];
            s[nb][2] = fexp(s[nb][2] - nm1); ls1 += s[nb][2];
            s[nb][3] = fexp(s[nb][3] - nm1); ls1 += s[nb][3];
        }
        ls0 += __shfl_xor_sync(0xffffffffu, ls0, 1);
        ls0 += __shfl_xor_sync(0xffffffffu, ls0, 2);
        ls1 += __shfl_xor_sync(0xffffffffu, ls1, 1);
        ls1 += __shfl_xor_sync(0xffffffffu, ls1, 2);
        l0 = l0 * corr0 + ls0;
        l1 = l1 * corr1 + ls1;

#pragma unroll
        for (int nb = 0; nb < 8; nb++) {
            o[nb][0] *= corr0; o[nb][1] *= corr0;
            o[nb][2] *= corr1; o[nb][3] *= corr1;
        }

        // ---- O += P V ----
#pragma unroll
        for (int kc = 0; kc < 4; kc++) {
            unsigned ah[4], al[4];
            {
                float* p0 = s[2 * kc];
                float* p1 = s[2 * kc + 1];
                split2(p0[0], p0[1], ah[0], al[0]);
                split2(p0[2], p0[3], ah[1], al[1]);
                split2(p1[0], p1[1], ah[2], al[2]);
                split2(p1[2], p1[3], ah[3], al[3]);
            }
#pragma unroll
            for (int nbp = 0; nbp < 4; nbp++) {
                unsigned Bh2[4], Bl2[4];
                uint32_t off = (uint32_t)(((kc * 16 + (lane & 15)) * GP2 +
                                           (nbp * 2 + ((lane >> 4) & 1)) * 8) * 2);
                ldm_x4t(Bh2, vh_u + off);
                ldm_x4t(Bl2, vl_u + off);
                mma_bf16(o[2 * nbp],     ah, &Bh2[0]);
                mma_bf16(o[2 * nbp + 1], ah, &Bh2[2]);
                mma_bf16(o[2 * nbp],     ah, &Bl2[0]);
                mma_bf16(o[2 * nbp + 1], ah, &Bl2[2]);
                mma_bf16(o[2 * nbp],     al, &Bh2[0]);
                mma_bf16(o[2 * nbp + 1], al, &Bh2[2]);
            }
        }

        if (kt + 1 < nkt) {
            CP_WAIT0;
            __syncthreads();
        }
    }

    // ---- epilogue: normalize, split hi/lo, write packed ----
    const float i0 = 1.f / l0, i1 = 1.f / l1;
#pragma unroll
    for (int nb = 0; nb < 8; nb++) {
        float a0 = o[nb][0] * i0, a1 = o[nb][1] * i0;
        float b0 = o[nb][2] * i1, b1 = o[nb][3] * i1;
        unsigned hp, lp;
        size_t o0 = (((size_t)(b * TT + rg0) * CC) + h * HD + nb * 8 + cbase) >> 1;
        split2(a0, a1, hp, lp); g_aoh[o0] = hp; g_aol[o0] = lp;
        size_t o1 = (((size_t)(b * TT + rg1) * CC) + h * HD + nb * 8 + cbase) >> 1;
        split2(b0, b1, hp, lp); g_aoh[o1] = hp; g_aol[o1] = lp;
    }
}

// ---------------------------------------------------------------------------
extern "C" void kernel_launch(void* const* d_in, const int* in_sizes, int n_in,
                              void* d_out, int out_size)
{
    const float* x     = (const float*)d_in[0];   // (4096,1024)
    const float* w_qkv = (const float*)d_in[1];   // (3072,1024)
    const float* w_out = (const float*)d_in[2];   // (1024,1024)
    float* out = (float*)d_out;                   // (4096,1024)

    float* qkv;  cudaGetSymbolAddress((void**)&qkv, g_qkv);
    void *xh, *xl, *wqh, *wql, *woh, *wol, *aoh, *aol;
    cudaGetSymbolAddress(&xh,  g_xh);  cudaGetSymbolAddress(&xl,  g_xl);
    cudaGetSymbolAddress(&wqh, g_wqh); cudaGetSymbolAddress(&wql, g_wql);
    cudaGetSymbolAddress(&woh, g_woh); cudaGetSymbolAddress(&wol, g_wol);
    cudaGetSymbolAddress(&aoh, g_aoh); cudaGetSymbolAddress(&aol, g_aol);

    const int M = BB * TT;

    static int attr_set = 0;
    if (!attr_set) {
        cudaFuncSetAttribute(gemm_ps,
                             cudaFuncAttributeMaxDynamicSharedMemorySize,
                             GEMM_SMEM_BYTES);
        cudaFuncSetAttribute(attn_mma,
                             cudaFuncAttributeMaxDynamicSharedMemorySize,
                             ATTN_SMEM_BYTES);
        attr_set = 1;
    }

    // pre-split inputs
    convert_pair<<<4096, 256>>>((const float4*)x, (uint2*)xh, (uint2*)xl, 1048576);
    convert_pair<<<3072, 256>>>((const float4*)w_qkv, (uint2*)wqh, (uint2*)wql, 786432);
    convert_pair<<<1024, 256>>>((const float4*)w_out, (uint2*)woh, (uint2*)wol, 262144);

    // 1) qkv = x @ w_qkv^T  (fp32 out)
    gemm_ps<<<dim3(C3 / 128, M / 256), 512, GEMM_SMEM_BYTES>>>(
        (const unsigned short*)xh, (const unsigned short*)xl,
        (const unsigned short*)wqh, (const unsigned short*)wql, qkv, M, C3, CC);

    // 2) RoPE + scale fold + split + head-major transpose
    convert_qkv_rope<<<(BB * TT * HH * 32 + 255) / 256, 256>>>();

    // 3) attention -> packed hi/lo attn-out
    attn_mma<<<dim3(TT / 128, BB * HH), 256, ATTN_SMEM_BYTES>>>();

    // 4) out = attn @ w_out^T
    gemm_ps<<<dim3(CC / 128, M / 256), 512, GEMM_SMEM_BYTES>>>(
        (const unsigned short*)aoh, (const unsigned short*)aol,
        (const unsigned short*)woh, (const unsigned short*)wol, out, M, CC, CC);
}

// round 8
// speedup vs baseline: 1.0986x; 1.0986x over previous
#include <cuda_runtime.h>
#include <cuda_bf16.h>
#include <math.h>
#include <stdint.h>

#define BB 2
#define TT 2048
#define CC 1024
#define HH 16
#define HD 64
#define C3 3072

__device__ float g_qkv[(size_t)BB * TT * C3];   // 4096 x 3072
__device__ float g_attn[(size_t)BB * TT * CC];  // 4096 x 1024

// ---------------------------------------------------------------------------
// mma / ldmatrix helpers
// ---------------------------------------------------------------------------
__device__ __forceinline__ void mma_bf16(float* c, const unsigned* a, const unsigned* b) {
    asm("mma.sync.aligned.m16n8k16.row.col.f32.bf16.bf16.f32 "
        "{%0,%1,%2,%3},{%4,%5,%6,%7},{%8,%9},{%0,%1,%2,%3};"
        : "+f"(c[0]), "+f"(c[1]), "+f"(c[2]), "+f"(c[3])
        : "r"(a[0]), "r"(a[1]), "r"(a[2]), "r"(a[3]), "r"(b[0]), "r"(b[1]));
}
__device__ __forceinline__ void ldm_x4(unsigned* r, uint32_t addr) {
    asm volatile("ldmatrix.sync.aligned.m8n8.x4.shared.b16 {%0,%1,%2,%3}, [%4];"
                 : "=r"(r[0]), "=r"(r[1]), "=r"(r[2]), "=r"(r[3]) : "r"(addr));
}
__device__ __forceinline__ void ldm_x4t(unsigned* r, uint32_t addr) {
    asm volatile("ldmatrix.sync.aligned.m8n8.x4.trans.shared.b16 {%0,%1,%2,%3}, [%4];"
                 : "=r"(r[0]), "=r"(r[1]), "=r"(r[2]), "=r"(r[3]) : "r"(addr));
}

__device__ __forceinline__ unsigned pack2bf(float lo, float hi) {
    unsigned r;
    asm("cvt.rn.bf16x2.f32 %0, %1, %2;" : "=r"(r) : "f"(hi), "f"(lo));
    return r;
}
__device__ __forceinline__ float bflo(unsigned u) { return __uint_as_float(u << 16); }
__device__ __forceinline__ float bfhi(unsigned u) { return __uint_as_float(u & 0xffff0000u); }

// fast exp on fma/alu pipes (no MUFU)
__device__ __forceinline__ float fexp(float x) {
    float y = x * 1.4426950408889634f;
    y = fmaxf(y, -126.0f);
    int ni = __float2int_rd(y);
    float f = y - (float)ni;
    float p = 0.0018775767f;
    p = fmaf(p, f, 0.0089893397f);
    p = fmaf(p, f, 0.0558282185f);
    p = fmaf(p, f, 0.2400789568f);
    p = fmaf(p, f, 0.6931531203f);
    p = fmaf(p, f, 0.9999999702f);
    return __uint_as_float(__float_as_uint(p) + ((unsigned)ni << 23));
}

__device__ __forceinline__ void split4(float4 v, uint2& hp, uint2& lp) {
    unsigned h01 = pack2bf(v.x, v.y);
    unsigned h23 = pack2bf(v.z, v.w);
    float r0 = v.x - bflo(h01);
    float r1 = v.y - bfhi(h01);
    float r2 = v.z - bflo(h23);
    float r3 = v.w - bfhi(h23);
    hp = make_uint2(h01, h23);
    lp = make_uint2(pack2bf(r0, r1), pack2bf(r2, r3));
}

// ---------------------------------------------------------------------------
// Tensor-core GEMM (NT), bf16 3-term split.
// CTA 128x128, BK=16, 256 threads (8 warps, 2x4), warp tile 64x32.
// 2 CTAs/SM so one CTA's mma covers the other's convert/sync bubbles.
// ---------------------------------------------------------------------------
#define GP 24
#define A_H (128 * GP)                  // 3072 halves
#define B_H (128 * GP)                  // 3072 halves
#define STAGE_H (2 * A_H + 2 * B_H)     // 12288 halves
#define GEMM_SMEM_BYTES (2 * STAGE_H * 2)   // 49152 B

__device__ __forceinline__ void cvt_store(unsigned short* hi_t, unsigned short* lo_t,
                                          int row, int col, float4 v) {
    uint2 hp, lp;
    split4(v, hp, lp);
    *(uint2*)&hi_t[row * GP + col] = hp;
    *(uint2*)&lo_t[row * GP + col] = lp;
}

__global__ __launch_bounds__(256, 2) void gemm_bf16x3(
    const float* __restrict__ A, const float* __restrict__ W,
    float* __restrict__ Cout, int M, int N, int K)
{
    extern __shared__ unsigned short sh[];

    const int tid = threadIdx.x;
    const int wid = tid >> 5;
    const int lane = tid & 31;
    const int warp_m = wid >> 2;        // 0..1 -> 64-row slices of 128
    const int warp_n = wid & 3;         // 0..3 -> 32-col slices of 128

    const float* Ap = A + (size_t)blockIdx.y * 128 * K;
    const float* Wp = W + (size_t)blockIdx.x * 128 * K;

    // 512 float4 slots per tile (128 rows x 4 chunks); thread covers rows r0, r0+64
    const int r0 = tid >> 2;
    const int c0 = (tid & 3) * 4;

    const uint32_t smem_u32 = (uint32_t)__cvta_generic_to_shared(sh);

    const int a_lrow = (lane & 7) + ((lane >> 3) & 1) * 8;
    const int a_lcol = ((lane >> 4) & 1) * 8;

    float acc[4][4][4];
#pragma unroll
    for (int i = 0; i < 4; i++)
#pragma unroll
        for (int j = 0; j < 4; j++)
#pragma unroll
            for (int q = 0; q < 4; q++) acc[i][j][q] = 0.f;

    const int nstage = K / 16;

    float4 va0 = *(const float4*)(Ap + (size_t)r0 * K + c0);
    float4 va1 = *(const float4*)(Ap + (size_t)(r0 + 64) * K + c0);
    float4 vb0 = *(const float4*)(Wp + (size_t)r0 * K + c0);
    float4 vb1 = *(const float4*)(Wp + (size_t)(r0 + 64) * K + c0);
    cvt_store(sh,           sh + A_H,           r0,      c0, va0);
    cvt_store(sh,           sh + A_H,           r0 + 64, c0, va1);
    cvt_store(sh + 2 * A_H, sh + 2 * A_H + B_H, r0,      c0, vb0);
    cvt_store(sh + 2 * A_H, sh + 2 * A_H + B_H, r0 + 64, c0, vb1);
    __syncthreads();

    for (int s = 0; s < nstage; s++) {
        if (s + 1 < nstage) {
            const int k0 = (s + 1) * 16;
            va0 = *(const float4*)(Ap + (size_t)r0 * K + k0 + c0);
            va1 = *(const float4*)(Ap + (size_t)(r0 + 64) * K + k0 + c0);
            vb0 = *(const float4*)(Wp + (size_t)r0 * K + k0 + c0);
            vb1 = *(const float4*)(Wp + (size_t)(r0 + 64) * K + k0 + c0);
        }
        {
            const uint32_t base = smem_u32 + (unsigned)(s & 1) * (STAGE_H * 2);
            const uint32_t baseAhi = base;
            const uint32_t baseAlo = base + A_H * 2;
            const uint32_t baseBhi = base + 2 * A_H * 2;
            const uint32_t baseBlo = base + (2 * A_H + B_H) * 2;

            // hold all B fragments (x4: two n-blocks per load)
            unsigned Bh[2][4], Bl[2][4];
#pragma unroll
            for (int anp = 0; anp < 2; anp++) {
                const uint32_t off = (uint32_t)(((warp_n * 32 + anp * 16 +
                                                  ((lane >> 4) & 1) * 8 + (lane & 7)) * GP +
                                                 ((lane >> 3) & 1) * 8) * 2);
                ldm_x4(Bh[anp], baseBhi + off);
                ldm_x4(Bl[anp], baseBlo + off);
            }
#pragma unroll
            for (int am = 0; am < 4; am++) {
                unsigned Ah[4], Al[4];
                const uint32_t off =
                    (uint32_t)(((warp_m * 64 + am * 16 + a_lrow) * GP + a_lcol) * 2);
                ldm_x4(Ah, baseAhi + off);
                ldm_x4(Al, baseAlo + off);
#pragma unroll
                for (int anp = 0; anp < 2; anp++) {
                    mma_bf16(acc[am][2 * anp],     Ah, &Bh[anp][0]);
                    mma_bf16(acc[am][2 * anp + 1], Ah, &Bh[anp][2]);
                    mma_bf16(acc[am][2 * anp],     Ah, &Bl[anp][0]);
                    mma_bf16(acc[am][2 * anp + 1], Ah, &Bl[anp][2]);
                    mma_bf16(acc[am][2 * anp],     Al, &Bh[anp][0]);
                    mma_bf16(acc[am][2 * anp + 1], Al, &Bh[anp][2]);
                }
            }
        }
        if (s + 1 < nstage) {
            unsigned short* st = sh + (unsigned)((s + 1) & 1) * STAGE_H;
            cvt_store(st,           st + A_H,           r0,      c0, va0);
            cvt_store(st,           st + A_H,           r0 + 64, c0, va1);
            cvt_store(st + 2 * A_H, st + 2 * A_H + B_H, r0,      c0, vb0);
            cvt_store(st + 2 * A_H, st + 2 * A_H + B_H, r0 + 64, c0, vb1);
            __syncthreads();
        }
    }

    const int mbase = blockIdx.y * 128 + warp_m * 64 + (lane >> 2);
    const int nbase = blockIdx.x * 128 + warp_n * 32 + (lane & 3) * 2;
#pragma unroll
    for (int am = 0; am < 4; am++) {
#pragma unroll
        for (int an = 0; an < 4; an++) {
            const int r = mbase + am * 16;
            const int c = nbase + an * 8;
            *(float2*)&Cout[(size_t)r * N + c]       = make_float2(acc[am][an][0], acc[am][an][1]);
            *(float2*)&Cout[(size_t)(r + 8) * N + c] = make_float2(acc[am][an][2], acc[am][an][3]);
        }
    }
}

// ---------------------------------------------------------------------------
// RoPE: in-place on q and k slices of g_qkv.
// ---------------------------------------------------------------------------
__global__ void rope_kernel()
{
    int i = blockIdx.x * blockDim.x + threadIdx.x;
    const int total = BB * TT * HH * (HD / 2);
    if (i >= total) return;

    int n = i >> 9;
    int r = i & 511;
    int h = r >> 5;
    int j = r & 31;
    int t = n & (TT - 1);

    float inv_freq = (float)exp(-(double)j * 0.28782313662425575);
    float f = (float)t * inv_freq;
    float c = cosf(f);
    float s = sinf(f);

    float* p = g_qkv + (size_t)n * C3 + h * HD + 2 * j;
    float qr = p[0], qi = p[1];
    p[0] = qr * c - qi * s;
    p[1] = qr * s + qi * c;

    float* pk = p + CC;
    float kr = pk[0], ki = pk[1];
    pk[0] = kr * c - ki * s;
    pk[1] = kr * s + ki * c;
}

// ---------------------------------------------------------------------------
// Tensor-core causal flash attention.
// CTA: 128 q-rows, 8 warps (16 rows/warp), 64-key tiles, dynamic smem.
// ---------------------------------------------------------------------------
#define GP2 72
#define KHI_O 0
#define KLO_O 4608
#define VHI_O 9216
#define VLO_O 13824
#define QHI_O 18432
#define QLO_O 27648
#define ATTN_SMEM_HALVES 36864
#define ATTN_SMEM_BYTES (ATTN_SMEM_HALVES * 2)   // 73728 B

__global__ __launch_bounds__(256) void attn_mma()
{
    extern __shared__ unsigned short ash[];

    const int bh = blockIdx.y;
    const int b = bh >> 4;
    const int h = bh & 15;
    const int qtile = 15 - blockIdx.x;     // heavy tiles first
    const int q0 = qtile * 128;
    const int tid = threadIdx.x;
    const int wid = tid >> 5;
    const int lane = tid & 31;
    const float scale = 0.125f;

    const float* base = g_qkv + (size_t)b * TT * C3;

    const uint32_t sm_u = (uint32_t)__cvta_generic_to_shared(ash);
    const uint32_t kh_u = sm_u + KHI_O * 2;
    const uint32_t kl_u = sm_u + KLO_O * 2;
    const uint32_t vh_u = sm_u + VHI_O * 2;
    const uint32_t vl_u = sm_u + VLO_O * 2;
    const uint32_t qh_u = sm_u + QHI_O * 2;
    const uint32_t ql_u = sm_u + QLO_O * 2;

    const int a_lrow = (lane & 7) + ((lane >> 3) & 1) * 8;
    const int a_lcol = ((lane >> 4) & 1) * 8;

    // ---- stage Q (128 x 64) ----
#pragma unroll
    for (int it = 0; it < 8; it++) {
        int idx = tid + it * 256;               // 2048 float4 slots
        int r = idx >> 4, c4 = (idx & 15) * 4;
        float4 v = *(const float4*)(base + (size_t)(q0 + r) * C3 + h * HD + c4);
        uint2 hp, lp;
        split4(v, hp, lp);
        *(uint2*)&ash[QHI_O + r * GP2 + c4] = hp;
        *(uint2*)&ash[QLO_O + r * GP2 + c4] = lp;
    }
    __syncthreads();

    unsigned Qh[4][4], Ql[4][4];
#pragma unroll
    for (int kk = 0; kk < 4; kk++) {
        uint32_t off = (uint32_t)(((wid * 16 + a_lrow) * GP2 + kk * 16 + a_lcol) * 2);
        ldm_x4(Qh[kk], qh_u + off);
        ldm_x4(Ql[kk], ql_u + off);
    }

    float o[8][4];
#pragma unroll
    for (int nb = 0; nb < 8; nb++)
#pragma unroll
        for (int e = 0; e < 4; e++) o[nb][e] = 0.f;
    float m0 = -1e30f, m1 = -1e30f, l0 = 0.f, l1 = 0.f;

    const int rg0 = q0 + wid * 16 + (lane >> 2);
    const int rg1 = rg0 + 8;
    const int cbase = (lane & 3) * 2;

    const int nkt = 2 * qtile + 2;
    for (int kt = 0; kt < nkt; kt++) {
        const int k0 = kt * 64;
        __syncthreads();

        // ---- load K,V tile (64 x 64), split bf16 hi/lo ----
#pragma unroll
        for (int it = 0; it < 4; it++) {
            int idx = tid + it * 256;            // 1024 slots
            int r = idx >> 4, c4 = (idx & 15) * 4;
            const float* src = base + (size_t)(k0 + r) * C3 + CC + h * HD + c4;
            float4 kv = *(const float4*)src;
            float4 vv = *(const float4*)(src + CC);
            uint2 hp, lp;
            split4(kv, hp, lp);
            *(uint2*)&ash[KHI_O + r * GP2 + c4] = hp;
            *(uint2*)&ash[KLO_O + r * GP2 + c4] = lp;
            split4(vv, hp, lp);
            *(uint2*)&ash[VHI_O + r * GP2 + c4] = hp;
            *(uint2*)&ash[VLO_O + r * GP2 + c4] = lp;
        }
        __syncthreads();

        // ---- S = Q K^T (3-pass split, x4 B loads) ----
        float s[8][4];
#pragma unroll
        for (int nb = 0; nb < 8; nb++)
#pragma unroll
            for (int e = 0; e < 4; e++) s[nb][e] = 0.f;

#pragma unroll
        for (int kk = 0; kk < 4; kk++) {
#pragma unroll
            for (int nbp = 0; nbp < 4; nbp++) {
                unsigned Bh[4], Bl[4];
                uint32_t off = (uint32_t)(((nbp * 16 + ((lane >> 4) & 1) * 8 + (lane & 7)) * GP2 +
                                           kk * 16 + ((lane >> 3) & 1) * 8) * 2);
                ldm_x4(Bh, kh_u + off);
                ldm_x4(Bl, kl_u + off);
                mma_bf16(s[2 * nbp],     Qh[kk], &Bh[0]);
                mma_bf16(s[2 * nbp + 1], Qh[kk], &Bh[2]);
                mma_bf16(s[2 * nbp],     Qh[kk], &Bl[0]);
                mma_bf16(s[2 * nbp + 1], Qh[kk], &Bl[2]);
                mma_bf16(s[2 * nbp],     Ql[kk], &Bh[0]);
                mma_bf16(s[2 * nbp + 1], Ql[kk], &Bh[2]);
            }
        }

        // ---- scale + causal mask ----
        const bool diag = (kt >= 2 * qtile);
#pragma unroll
        for (int nb = 0; nb < 8; nb++) {
            int c0g = k0 + nb * 8 + cbase;
#pragma unroll
            for (int e = 0; e < 4; e++) {
                int col = c0g + (e & 1);
                int row = (e < 2) ? rg0 : rg1;
                float v = s[nb][e] * scale;
                if (diag && col > row) v = -1e30f;
                s[nb][e] = v;
            }
        }

        // ---- online softmax ----
        float mx0 = -1e30f, mx1 = -1e30f;
#pragma unroll
        for (int nb = 0; nb < 8; nb++) {
            mx0 = fmaxf(mx0, fmaxf(s[nb][0], s[nb][1]));
            mx1 = fmaxf(mx1, fmaxf(s[nb][2], s[nb][3]));
        }
        mx0 = fmaxf(mx0, __shfl_xor_sync(0xffffffffu, mx0, 1));
        mx0 = fmaxf(mx0, __shfl_xor_sync(0xffffffffu, mx0, 2));
        mx1 = fmaxf(mx1, __shfl_xor_sync(0xffffffffu, mx1, 1));
        mx1 = fmaxf(mx1, __shfl_xor_sync(0xffffffffu, mx1, 2));

        float nm0 = fmaxf(m0, mx0), nm1 = fmaxf(m1, mx1);
        float corr0 = fexp(m0 - nm0), corr1 = fexp(m1 - nm1);
        m0 = nm0; m1 = nm1;

        float ls0 = 0.f, ls1 = 0.f;
#pragma unroll
        for (int nb = 0; nb < 8; nb++) {
            s[nb][0] = fexp(s[nb][0] - nm0); ls0 += s[nb][0];
            s[nb][1] = fexp(s[nb][1] - nm0); ls0 += s[nb][1];
            s[nb][2] = fexp(s[nb][2] - nm1); ls1 += s[nb][2];
            s[nb][3] = fexp(s[nb][3] - nm1); ls1 += s[nb][3];
        }
        ls0 += __shfl_xor_sync(0xffffffffu, ls0, 1);
        ls0 += __shfl_xor_sync(0xffffffffu, ls0, 2);
        ls1 += __shfl_xor_sync(0xffffffffu, ls1, 1);
        ls1 += __shfl_xor_sync(0xffffffffu, ls1, 2);
        l0 = l0 * corr0 + ls0;
        l1 = l1 * corr1 + ls1;

#pragma unroll
        for (int nb = 0; nb < 8; nb++) {
            o[nb][0] *= corr0; o[nb][1] *= corr0;
            o[nb][2] *= corr1; o[nb][3] *= corr1;
        }

        // ---- O += P V (3-pass split, x4 trans B loads) ----
#pragma unroll
        for (int kc = 0; kc < 4; kc++) {
            unsigned ah[4], al[4];
            {
                float* p0 = s[2 * kc];
                float* p1 = s[2 * kc + 1];
                ah[0] = pack2bf(p0[0], p0[1]);
                ah[1] = pack2bf(p0[2], p0[3]);
                ah[2] = pack2bf(p1[0], p1[1]);
                ah[3] = pack2bf(p1[2], p1[3]);
                al[0] = pack2bf(p0[0] - bflo(ah[0]), p0[1] - bfhi(ah[0]));
                al[1] = pack2bf(p0[2] - bflo(ah[1]), p0[3] - bfhi(ah[1]));
                al[2] = pack2bf(p1[0] - bflo(ah[2]), p1[1] - bfhi(ah[2]));
                al[3] = pack2bf(p1[2] - bflo(ah[3]), p1[3] - bfhi(ah[3]));
            }
#pragma unroll
            for (int nbp = 0; nbp < 4; nbp++) {
                unsigned Bh[4], Bl[4];
                uint32_t off = (uint32_t)(((kc * 16 + (lane & 15)) * GP2 +
                                           (nbp * 2 + ((lane >> 4) & 1)) * 8) * 2);
                ldm_x4t(Bh, vh_u + off);
                ldm_x4t(Bl, vl_u + off);
                mma_bf16(o[2 * nbp],     ah, &Bh[0]);
                mma_bf16(o[2 * nbp + 1], ah, &Bh[2]);
                mma_bf16(o[2 * nbp],     ah, &Bl[0]);
                mma_bf16(o[2 * nbp + 1], ah, &Bl[2]);
                mma_bf16(o[2 * nbp],     al, &Bh[0]);
                mma_bf16(o[2 * nbp + 1], al, &Bh[2]);
            }
        }
    }

    // ---- epilogue ----
    const float i0 = 1.f / l0, i1 = 1.f / l1;
    float* out0 = g_attn + (size_t)(b * TT + rg0) * CC + h * HD + cbase;
    float* out1 = g_attn + (size_t)(b * TT + rg1) * CC + h * HD + cbase;
#pragma unroll
    for (int nb = 0; nb < 8; nb++) {
        *(float2*)(out0 + nb * 8) = make_float2(o[nb][0] * i0, o[nb][1] * i0);
        *(float2*)(out1 + nb * 8) = make_float2(o[nb][2] * i1, o[nb][3] * i1);
    }
}

// ---------------------------------------------------------------------------
extern "C" void kernel_launch(void* const* d_in, const int* in_sizes, int n_in,
                              void* d_out, int out_size)
{
    const float* x     = (const float*)d_in[0];   // (4096,1024)
    const float* w_qkv = (const float*)d_in[1];   // (3072,1024)
    const float* w_out = (const float*)d_in[2];   // (1024,1024)
    float* out = (float*)d_out;                   // (4096,1024)

    float* qkv;  cudaGetSymbolAddress((void**)&qkv,  g_qkv);
    float* attn; cudaGetSymbolAddress((void**)&attn, g_attn);

    const int M = BB * TT;

    static int attr_set = 0;
    if (!attr_set) {
        cudaFuncSetAttribute(gemm_bf16x3,
                             cudaFuncAttributeMaxDynamicSharedMemorySize,
                             GEMM_SMEM_BYTES);
        cudaFuncSetAttribute(attn_mma,
                             cudaFuncAttributeMaxDynamicSharedMemorySize,
                             ATTN_SMEM_BYTES);
        attr_set = 1;
    }

    gemm_bf16x3<<<dim3(C3 / 128, M / 128), 256, GEMM_SMEM_BYTES>>>(x, w_qkv, qkv, M, C3, CC);

    const int rope_total = BB * TT * HH * (HD / 2);
    rope_kernel<<<(rope_total + 255) / 256, 256>>>();

    attn_mma<<<dim3(TT / 128, BB * HH), 256, ATTN_SMEM_BYTES>>>();

    gemm_bf16x3<<<dim3(CC / 128, M / 128), 256, GEMM_SMEM_BYTES>>>(attn, w_out, out, M, CC, CC);
}